// round 3
// baseline (speedup 1.0000x reference)
#include <cuda_runtime.h>
#include <math.h>

#define NU 100000
#define NI 50000
#define DD 64
#define ES 800000
#define EUI 1000000
#define EIU 1000000
#define ETOT (ES + EUI + EIU)
#define NROWS (2 * NU + NI)
#define NSCANBLK ((NROWS + 2047) / 2048)
#define ALPHA_LRELU 0.2f
#define CDIV(a,b) (((a)+(b)-1)/(b))

// ---------------- scratch (device globals; no runtime allocation) -------------
__device__ float2 g_v12[ETOT];            // edge att (layer1, layer2), row-sorted
__device__ int    g_colp[ETOT];           // col, row-sorted
__device__ int    g_cnt[NROWS];
__device__ int    g_rowptr[NROWS + 1];
__device__ int    g_cursor[NROWS];
__device__ int    g_bsum[NSCANBLK + 1];
__device__ float4 g_node[(2*NU + 2*NI) * 16];   // u1, u2, i1, i2 (64 floats = 16 float4 each)

// ---------------- helpers ------------------------------------------------------
__device__ __forceinline__ float warp_sum(float v) {
    #pragma unroll
    for (int o = 16; o; o >>= 1) v += __shfl_xor_sync(0xffffffffu, v, o);
    return v;
}
__device__ __forceinline__ float warp_max(float v) {
    #pragma unroll
    for (int o = 16; o; o >>= 1) v = fmaxf(v, __shfl_xor_sync(0xffffffffu, v, o));
    return v;
}
__device__ __forceinline__ float att_scalar(float dot, float b1, float w2, float b2) {
    float h = tanhf(dot + b1);
    float g = h * w2 + b2;
    g = g > 0.f ? g : ALPHA_LRELU * g;
    return expf(g);
}

// ---------------- CSR build ----------------------------------------------------
__global__ void k_zero_int(int* __restrict__ p, int n) {
    int i = blockIdx.x * blockDim.x + threadIdx.x;
    if (i < n) p[i] = 0;
}

__global__ void k_hist4(const int4* __restrict__ row, int rowbase, int n4, int* __restrict__ cnt) {
    int i = blockIdx.x * blockDim.x + threadIdx.x;
    if (i >= n4) return;
    int4 r = row[i];
    atomicAdd(cnt + rowbase + r.x, 1);
    atomicAdd(cnt + rowbase + r.y, 1);
    atomicAdd(cnt + rowbase + r.z, 1);
    atomicAdd(cnt + rowbase + r.w, 1);
}

__global__ void __launch_bounds__(1024) k_scan1(const int* __restrict__ cnt,
                                                int* __restrict__ out,
                                                int* __restrict__ bsum, int n) {
    __shared__ int sh[1024];
    int t = threadIdx.x;
    int i0 = blockIdx.x * 2048 + 2 * t;
    int c0 = (i0 < n) ? cnt[i0] : 0;
    int c1 = (i0 + 1 < n) ? cnt[i0 + 1] : 0;
    int p = c0 + c1;
    sh[t] = p;
    __syncthreads();
    #pragma unroll
    for (int off = 1; off < 1024; off <<= 1) {
        int add = (t >= off) ? sh[t - off] : 0;
        __syncthreads();
        sh[t] += add;
        __syncthreads();
    }
    int excl = sh[t] - p;
    if (i0 < n) out[i0] = excl;
    if (i0 + 1 < n) out[i0 + 1] = excl + c0;
    if (t == 1023) bsum[blockIdx.x] = sh[t];
}

__global__ void __launch_bounds__(256) k_scan2(int* __restrict__ bsum, int nb) {
    __shared__ int sh[256];
    int t = threadIdx.x;
    int v = (t < nb) ? bsum[t] : 0;
    sh[t] = v;
    __syncthreads();
    #pragma unroll
    for (int off = 1; off < 256; off <<= 1) {
        int add = (t >= off) ? sh[t - off] : 0;
        __syncthreads();
        sh[t] += add;
        __syncthreads();
    }
    if (t < nb) bsum[t] = sh[t] - v;
}

__global__ void k_scan3(int* __restrict__ rowptr, int* __restrict__ cursor,
                        const int* __restrict__ bsum, int n) {
    int i = blockIdx.x * blockDim.x + threadIdx.x;
    if (i < n) {
        int v = rowptr[i] + bsum[i >> 11];
        rowptr[i] = v;
        cursor[i] = v;
    }
    if (i == 0) rowptr[n] = ETOT;
}

// scatter + fused edge logit, 4 edges/thread
__global__ void k_scatter4(const int4* __restrict__ row, const int4* __restrict__ col,
                           const float4* __restrict__ raw1, const float4* __restrict__ raw2,
                           const float* __restrict__ law, const float* __restrict__ lab,
                           int j1, int j2, int rowbase, int n4,
                           int* __restrict__ cursor, int* __restrict__ colp,
                           float2* __restrict__ v12) {
    int i = blockIdx.x * blockDim.x + threadIdx.x;
    if (i >= n4) return;
    float w1 = law[j1], b1 = lab[j1], w2 = law[j2], b2 = lab[j2];
    int4 r = row[i];
    int4 c = col[i];
    float4 a = raw1[i];
    float4 b = raw2[i];
    int rr[4] = {r.x, r.y, r.z, r.w};
    int cc[4] = {c.x, c.y, c.z, c.w};
    float aa[4] = {a.x, a.y, a.z, a.w};
    float bb[4] = {b.x, b.y, b.z, b.w};
    #pragma unroll
    for (int k = 0; k < 4; k++) {
        float x1 = aa[k] * w1 + b1;
        float x2 = bb[k] * w2 + b2;
        float v1 = expf(1.f / (1.f + expf(-x1)));
        float v2 = expf(1.f / (1.f + expf(-x2)));
        int pos = atomicAdd(cursor + rowbase + rr[k], 1);
        colp[pos] = cc[k];
        v12[pos] = make_float2(v1, v2);
    }
}

// row softmax over both components, in place, warp per row
__global__ void __launch_bounds__(256) k_softmax(const int* __restrict__ rowptr,
                                                 float2* __restrict__ v12) {
    int r = (blockIdx.x * blockDim.x + threadIdx.x) >> 5;
    int lane = threadIdx.x & 31;
    if (r >= NROWS) return;
    int s = rowptr[r], e = rowptr[r + 1];
    int len = e - s;
    if (len == 0) return;
    if (len <= 128) {
        float2 vals[4];
        int cnt = 0;
        float m1 = -1e30f, m2 = -1e30f;
        for (int j = s + lane; j < e; j += 32) {
            float2 v = v12[j];
            vals[cnt++] = v;
            m1 = fmaxf(m1, v.x); m2 = fmaxf(m2, v.y);
        }
        m1 = warp_max(m1); m2 = warp_max(m2);
        float s1 = 0.f, s2 = 0.f;
        #pragma unroll
        for (int k = 0; k < 4; k++) if (k < cnt) {
            vals[k].x = expf(vals[k].x - m1);
            vals[k].y = expf(vals[k].y - m2);
            s1 += vals[k].x; s2 += vals[k].y;
        }
        s1 = warp_sum(s1); s2 = warp_sum(s2);
        float inv1 = 1.f / (s1 + 1e-12f), inv2 = 1.f / (s2 + 1e-12f);
        int k = 0;
        for (int j = s + lane; j < e; j += 32, k++)
            v12[j] = make_float2(vals[k].x * inv1, vals[k].y * inv2);
    } else {
        float m1 = -1e30f, m2 = -1e30f;
        for (int j = s + lane; j < e; j += 32) {
            float2 v = v12[j];
            m1 = fmaxf(m1, v.x); m2 = fmaxf(m2, v.y);
        }
        m1 = warp_max(m1); m2 = warp_max(m2);
        float s1 = 0.f, s2 = 0.f;
        for (int j = s + lane; j < e; j += 32) {
            float2 v = v12[j];
            s1 += expf(v.x - m1); s2 += expf(v.y - m2);
        }
        s1 = warp_sum(s1); s2 = warp_sum(s2);
        float inv1 = 1.f / (s1 + 1e-12f), inv2 = 1.f / (s2 + 1e-12f);
        for (int j = s + lane; j < e; j += 32) {
            float2 v = v12[j];
            v12[j] = make_float2(expf(v.x - m1) * inv1, expf(v.y - m2) * inv2);
        }
    }
}

// SpMM row: float4 per lane, 2 edges per iteration. Result valid in lanes 0-15.
template<int COMP>
__device__ __forceinline__ float4 spmm4(const float2* __restrict__ v12,
                                        const int* __restrict__ colp,
                                        int s, int e,
                                        const float4* __restrict__ x4, int lane) {
    float4 acc = make_float4(0.f, 0.f, 0.f, 0.f);
    int half = lane >> 4;
    int q = lane & 15;
    for (int j = s; j < e; j += 2) {
        int jj = j + half;
        int cl = 0; float wl = 0.f;
        if (q == 0 && jj < e) {
            cl = __ldg(colp + jj);
            float2 v = __ldg(v12 + jj);
            wl = COMP ? v.y : v.x;
        }
        int c  = __shfl_sync(0xffffffffu, cl, lane & 16);
        float w = __shfl_sync(0xffffffffu, wl, lane & 16);
        float4 x = __ldg(x4 + (size_t)c * 16 + q);
        acc.x += w * x.x; acc.y += w * x.y; acc.z += w * x.z; acc.w += w * x.w;
    }
    acc.x += __shfl_down_sync(0xffffffffu, acc.x, 16);
    acc.y += __shfl_down_sync(0xffffffffu, acc.y, 16);
    acc.z += __shfl_down_sync(0xffffffffu, acc.z, 16);
    acc.w += __shfl_down_sync(0xffffffffu, acc.w, 16);
    return acc;
}

// fused: both user SpMMs + attention combine -> u_out  (warp per user node)
template<int COMP>
__global__ void __launch_bounds__(256) k_user_fused(const float4* __restrict__ uprev,
                                                    const float4* __restrict__ iprev,
                                                    const float2* __restrict__ v12,
                                                    const int* __restrict__ colp,
                                                    const int* __restrict__ rowptr,
                                                    const float* __restrict__ a1W,
                                                    const float* __restrict__ a1b,
                                                    const float* __restrict__ a2w,
                                                    const float* __restrict__ a2b,
                                                    int k, float4* __restrict__ out) {
    int node = (blockIdx.x * blockDim.x + threadIdx.x) >> 5;
    int lane = threadIdx.x & 31;
    if (node >= NU) return;
    int s_sn = __ldg(rowptr + node),      e_sn = __ldg(rowptr + node + 1);
    int s_ci = __ldg(rowptr + NU + node), e_ci = __ldg(rowptr + NU + node + 1);
    float4 fu = spmm4<COMP>(v12, colp, s_sn, e_sn, uprev, lane);   // u_from_u
    float4 fi = spmm4<COMP>(v12, colp, s_ci, e_ci, iprev, lane);   // u_from_i
    int q = lane & 15;
    float4 u = make_float4(0.f, 0.f, 0.f, 0.f);
    float dint = 0.f, dsoc = 0.f;
    const float4* Wa = (const float4*)(a1W + (size_t)k * 128);
    const float4* Wb = Wa + 32;
    if (lane < 16) {
        u = __ldg(uprev + (size_t)node * 16 + q);
        float4 wa0 = __ldg(Wa + q), wa1 = __ldg(Wa + 16 + q);
        float4 wb0 = __ldg(Wb + q), wb1 = __ldg(Wb + 16 + q);
        dint = u.x*wa0.x + u.y*wa0.y + u.z*wa0.z + u.w*wa0.w
             + fi.x*wa1.x + fi.y*wa1.y + fi.z*wa1.z + fi.w*wa1.w;
        dsoc = u.x*wb0.x + u.y*wb0.y + u.z*wb0.z + u.w*wb0.w
             + fu.x*wb1.x + fu.y*wb1.y + fu.z*wb1.z + fu.w*wb1.w;
    }
    dint = warp_sum(dint); dsoc = warp_sum(dsoc);
    float aint = att_scalar(dint, a1b[k],     a2w[k],     a2b[k])     + 0.7f;
    float asoc = att_scalar(dsoc, a1b[k + 1], a2w[k + 1], a2b[k + 1]) + 0.3f;
    float sden = aint + asoc;
    float wi = 0.5f * aint / sden, ws = 0.5f * asoc / sden;
    if (lane < 16) {
        float4 o;
        o.x = 0.5f * u.x + wi * fi.x + ws * fu.x;
        o.y = 0.5f * u.y + wi * fi.y + ws * fu.y;
        o.z = 0.5f * u.z + wi * fi.z + ws * fu.z;
        o.w = 0.5f * u.w + wi * fi.w + ws * fu.w;
        out[(size_t)node * 16 + q] = o;
    }
}

// fused: item SpMM + combine -> i_out  (warp per item node)
template<int COMP>
__global__ void __launch_bounds__(256) k_item_fused(const float4* __restrict__ uprev,
                                                    const float4* __restrict__ iprev,
                                                    const float2* __restrict__ v12,
                                                    const int* __restrict__ colp,
                                                    const int* __restrict__ rowptr,
                                                    const float* __restrict__ a1W,
                                                    const float* __restrict__ a1b,
                                                    const float* __restrict__ a2w,
                                                    const float* __restrict__ a2b,
                                                    int k, float4* __restrict__ out) {
    int node = (blockIdx.x * blockDim.x + threadIdx.x) >> 5;
    int lane = threadIdx.x & 31;
    if (node >= NI) return;
    int s_ic = __ldg(rowptr + 2 * NU + node), e_ic = __ldg(rowptr + 2 * NU + node + 1);
    float4 f = spmm4<COMP>(v12, colp, s_ic, e_ic, uprev, lane);   // i_from_u
    int q = lane & 15;
    float4 it = make_float4(0.f, 0.f, 0.f, 0.f);
    float dself = 0.f, dcust = 0.f;
    const float4* Wa = (const float4*)(a1W + (size_t)k * 128);
    const float4* Wb = Wa + 32;
    if (lane < 16) {
        it = __ldg(iprev + (size_t)node * 16 + q);
        float4 wa0 = __ldg(Wa + q), wa1 = __ldg(Wa + 16 + q);
        float4 wb0 = __ldg(Wb + q), wb1 = __ldg(Wb + 16 + q);
        dself = it.x*(wa0.x+wa1.x) + it.y*(wa0.y+wa1.y) + it.z*(wa0.z+wa1.z) + it.w*(wa0.w+wa1.w);
        dcust = it.x*wb0.x + it.y*wb0.y + it.z*wb0.z + it.w*wb0.w
              + f.x*wb1.x + f.y*wb1.y + f.z*wb1.z + f.w*wb1.w;
    }
    dself = warp_sum(dself); dcust = warp_sum(dcust);
    float aself = att_scalar(dself, a1b[k],     a2w[k],     a2b[k])     + 1.0f;
    float acust = att_scalar(dcust, a1b[k + 1], a2w[k + 1], a2b[k + 1]) + 1.0f;
    float sden = aself + acust;
    float wsf = aself / sden, wcu = acust / sden;
    if (lane < 16) {
        float4 o;
        o.x = wsf * it.x + wcu * f.x;
        o.y = wsf * it.y + wcu * f.y;
        o.z = wsf * it.z + wcu * f.z;
        o.w = wsf * it.w + wcu * f.w;
        out[(size_t)node * 16 + q] = o;
    }
}

// final scorer: warp per (user, item) pair
__global__ void __launch_bounds__(256) k_final(const float4* __restrict__ u0,
                                               const float4* __restrict__ u1,
                                               const float4* __restrict__ u2,
                                               const float4* __restrict__ i0,
                                               const float4* __restrict__ i1,
                                               const float4* __restrict__ i2,
                                               const int* __restrict__ uidx,
                                               const int* __restrict__ iidx,
                                               float* __restrict__ out, int B) {
    int b = (blockIdx.x * blockDim.x + threadIdx.x) >> 5;
    int lane = threadIdx.x & 31;
    if (b >= B) return;
    float d = 0.f;
    if (lane < 16) {
        size_t uo = (size_t)__ldg(uidx + b) * 16 + lane;
        size_t io = (size_t)__ldg(iidx + b) * 16 + lane;
        float4 a0 = __ldg(u0 + uo), c0 = __ldg(i0 + io);
        float4 a1 = __ldg(u1 + uo), c1 = __ldg(i1 + io);
        float4 a2 = __ldg(u2 + uo), c2 = __ldg(i2 + io);
        d = a0.x*c0.x + a0.y*c0.y + a0.z*c0.z + a0.w*c0.w
          + a1.x*c1.x + a1.y*c1.y + a1.z*c1.z + a1.w*c1.w
          + a2.x*c2.x + a2.y*c2.y + a2.z*c2.z + a2.w*c2.w;
    }
    d = warp_sum(d);
    if (lane == 0) out[b] = 1.f / (1.f + expf(-d));
}

// ---------------- launch ------------------------------------------------------
extern "C" void kernel_launch(void* const* d_in, const int* in_sizes, int n_in,
                              void* d_out, int out_size) {
    const float* u_emb = (const float*)d_in[0];
    const float* i_emb = (const float*)d_in[1];
    const float* snii1 = (const float*)d_in[2];
    const float* snii2 = (const float*)d_in[3];
    const float* ciii1 = (const float*)d_in[4];
    const float* ciii2 = (const float*)d_in[5];
    const float* icii1 = (const float*)d_in[6];
    const float* icii2 = (const float*)d_in[7];
    const float* law   = (const float*)d_in[8];
    const float* lab   = (const float*)d_in[9];
    const float* a1W   = (const float*)d_in[10];
    const float* a1b   = (const float*)d_in[11];
    const float* a2w   = (const float*)d_in[12];
    const float* a2b   = (const float*)d_in[13];
    const int* sn_row  = (const int*)d_in[14];
    const int* sn_col  = (const int*)d_in[15];
    const int* ci_row  = (const int*)d_in[16];
    const int* ci_col  = (const int*)d_in[17];
    const int* ic_row  = (const int*)d_in[18];
    const int* ic_col  = (const int*)d_in[19];
    const int* uidx    = (const int*)d_in[20];
    const int* iidx    = (const int*)d_in[21];
    float* out = (float*)d_out;
    int B = out_size;

    float2 *v12; int *colp, *cnt, *rowptr, *cursor, *bsum; float4 *np;
    cudaGetSymbolAddress((void**)&v12, g_v12);
    cudaGetSymbolAddress((void**)&colp, g_colp);
    cudaGetSymbolAddress((void**)&cnt, g_cnt);
    cudaGetSymbolAddress((void**)&rowptr, g_rowptr);
    cudaGetSymbolAddress((void**)&cursor, g_cursor);
    cudaGetSymbolAddress((void**)&bsum, g_bsum);
    cudaGetSymbolAddress((void**)&np, g_node);

    float4* u1 = np;
    float4* u2 = u1 + (size_t)NU * 16;
    float4* i1 = u2 + (size_t)NU * 16;
    float4* i2 = i1 + (size_t)NI * 16;
    const float4* u0 = (const float4*)u_emb;
    const float4* i0 = (const float4*)i_emb;

    const int T = 256;

    // ---- CSR build ----
    k_zero_int<<<CDIV(NROWS, T), T>>>(cnt, NROWS);
    k_hist4<<<CDIV(ES/4, T), T>>>((const int4*)sn_row, 0, ES/4, cnt);
    k_hist4<<<CDIV(EUI/4, T), T>>>((const int4*)ci_row, NU, EUI/4, cnt);
    k_hist4<<<CDIV(EIU/4, T), T>>>((const int4*)ic_row, 2*NU, EIU/4, cnt);
    k_scan1<<<NSCANBLK, 1024>>>(cnt, rowptr, bsum, NROWS);
    k_scan2<<<1, 256>>>(bsum, NSCANBLK);
    k_scan3<<<CDIV(NROWS, T), T>>>(rowptr, cursor, bsum, NROWS);

    // ---- scatter (with fused edge logits) ----
    k_scatter4<<<CDIV(ES/4, T), T>>>((const int4*)sn_row, (const int4*)sn_col,
                                     (const float4*)snii1, (const float4*)snii2,
                                     law, lab, 0, 1, 0, ES/4, cursor, colp, v12);
    k_scatter4<<<CDIV(EUI/4, T), T>>>((const int4*)ci_row, (const int4*)ci_col,
                                      (const float4*)ciii1, (const float4*)ciii2,
                                      law, lab, 2, 3, NU, EUI/4, cursor, colp, v12);
    k_scatter4<<<CDIV(EIU/4, T), T>>>((const int4*)ic_row, (const int4*)ic_col,
                                      (const float4*)icii1, (const float4*)icii2,
                                      law, lab, 4, 5, 2*NU, EIU/4, cursor, colp, v12);

    // ---- row softmax ----
    k_softmax<<<CDIV(NROWS * 32, T), T>>>(rowptr, v12);

    // ---- layer 1 (fused SpMM + combine) ----
    k_user_fused<0><<<CDIV(NU * 32, T), T>>>(u0, i0, v12, colp, rowptr, a1W, a1b, a2w, a2b, 0, u1);
    k_item_fused<0><<<CDIV(NI * 32, T), T>>>(u0, i0, v12, colp, rowptr, a1W, a1b, a2w, a2b, 4, i1);

    // ---- layer 2 ----
    k_user_fused<1><<<CDIV(NU * 32, T), T>>>(u1, i1, v12, colp, rowptr, a1W, a1b, a2w, a2b, 2, u2);
    k_item_fused<1><<<CDIV(NI * 32, T), T>>>(u1, i1, v12, colp, rowptr, a1W, a1b, a2w, a2b, 6, i2);

    // ---- final ----
    k_final<<<CDIV(B * 32, T), T>>>(u0, u1, u2, i0, i1, i2, uidx, iidx, out, B);
}

// round 4
// speedup vs baseline: 1.0857x; 1.0857x over previous
#include <cuda_runtime.h>
#include <math.h>

#define NU 100000
#define NI 50000
#define DD 64
#define ES 800000
#define EUI 1000000
#define EIU 1000000
#define ETOT (ES + EUI + EIU)
#define NROWS (2 * NU + NI)
#define NSCANBLK ((NROWS + 2047) / 2048)
#define ALPHA_LRELU 0.2f
#define CDIV(a,b) (((a)+(b)-1)/(b))

// ---------------- scratch (device globals; no runtime allocation) -------------
__device__ float2 g_v12[ETOT];            // edge att (layer1, layer2), row-sorted
__device__ int    g_colp[ETOT];           // col, row-sorted
__device__ int    g_cnt[NROWS];
__device__ int    g_rowptr[NROWS + 1];
__device__ int    g_cursor[NROWS];
__device__ int    g_bsum[NSCANBLK + 1];
__device__ float4 g_node[(2*NU + 2*NI) * 16];   // u1, u2, i1, i2

// ---------------- helpers ------------------------------------------------------
__device__ __forceinline__ float warp_sum(float v) {
    #pragma unroll
    for (int o = 16; o; o >>= 1) v += __shfl_xor_sync(0xffffffffu, v, o);
    return v;
}
__device__ __forceinline__ float warp_max(float v) {
    #pragma unroll
    for (int o = 16; o; o >>= 1) v = fmaxf(v, __shfl_xor_sync(0xffffffffu, v, o));
    return v;
}
__device__ __forceinline__ float att_scalar(float dot, float b1, float w2, float b2) {
    float h = tanhf(dot + b1);
    float g = h * w2 + b2;
    g = g > 0.f ? g : ALPHA_LRELU * g;
    return expf(g);
}

// ---------------- CSR build ----------------------------------------------------
__global__ void k_zero_int(int* __restrict__ p, int n) {
    int i = blockIdx.x * blockDim.x + threadIdx.x;
    if (i < n) p[i] = 0;
}

__global__ void k_hist4(const int4* __restrict__ row, int rowbase, int n4, int* __restrict__ cnt) {
    int i = blockIdx.x * blockDim.x + threadIdx.x;
    if (i >= n4) return;
    int4 r = row[i];
    atomicAdd(cnt + rowbase + r.x, 1);
    atomicAdd(cnt + rowbase + r.y, 1);
    atomicAdd(cnt + rowbase + r.z, 1);
    atomicAdd(cnt + rowbase + r.w, 1);
}

__global__ void __launch_bounds__(1024) k_scan1(const int* __restrict__ cnt,
                                                int* __restrict__ out,
                                                int* __restrict__ bsum, int n) {
    __shared__ int sh[1024];
    int t = threadIdx.x;
    int i0 = blockIdx.x * 2048 + 2 * t;
    int c0 = (i0 < n) ? cnt[i0] : 0;
    int c1 = (i0 + 1 < n) ? cnt[i0 + 1] : 0;
    int p = c0 + c1;
    sh[t] = p;
    __syncthreads();
    #pragma unroll
    for (int off = 1; off < 1024; off <<= 1) {
        int add = (t >= off) ? sh[t - off] : 0;
        __syncthreads();
        sh[t] += add;
        __syncthreads();
    }
    int excl = sh[t] - p;
    if (i0 < n) out[i0] = excl;
    if (i0 + 1 < n) out[i0 + 1] = excl + c0;
    if (t == 1023) bsum[blockIdx.x] = sh[t];
}

__global__ void __launch_bounds__(256) k_scan2(int* __restrict__ bsum, int nb) {
    __shared__ int sh[256];
    int t = threadIdx.x;
    int v = (t < nb) ? bsum[t] : 0;
    sh[t] = v;
    __syncthreads();
    #pragma unroll
    for (int off = 1; off < 256; off <<= 1) {
        int add = (t >= off) ? sh[t - off] : 0;
        __syncthreads();
        sh[t] += add;
        __syncthreads();
    }
    if (t < nb) bsum[t] = sh[t] - v;
}

__global__ void k_scan3(int* __restrict__ rowptr, int* __restrict__ cursor,
                        const int* __restrict__ bsum, int n) {
    int i = blockIdx.x * blockDim.x + threadIdx.x;
    if (i < n) {
        int v = rowptr[i] + bsum[i >> 11];
        rowptr[i] = v;
        cursor[i] = v;
    }
    if (i == 0) rowptr[n] = ETOT;
}

// scatter + fused edge logit, 4 edges/thread
__global__ void k_scatter4(const int4* __restrict__ row, const int4* __restrict__ col,
                           const float4* __restrict__ raw1, const float4* __restrict__ raw2,
                           const float* __restrict__ law, const float* __restrict__ lab,
                           int j1, int j2, int rowbase, int n4,
                           int* __restrict__ cursor, int* __restrict__ colp,
                           float2* __restrict__ v12) {
    int i = blockIdx.x * blockDim.x + threadIdx.x;
    if (i >= n4) return;
    float w1 = law[j1], b1 = lab[j1], w2 = law[j2], b2 = lab[j2];
    int4 r = row[i];
    int4 c = col[i];
    float4 a = raw1[i];
    float4 b = raw2[i];
    int rr[4] = {r.x, r.y, r.z, r.w};
    int cc[4] = {c.x, c.y, c.z, c.w};
    float aa[4] = {a.x, a.y, a.z, a.w};
    float bb[4] = {b.x, b.y, b.z, b.w};
    #pragma unroll
    for (int k = 0; k < 4; k++) {
        float x1 = aa[k] * w1 + b1;
        float x2 = bb[k] * w2 + b2;
        float v1 = expf(1.f / (1.f + expf(-x1)));
        float v2 = expf(1.f / (1.f + expf(-x2)));
        int pos = atomicAdd(cursor + rowbase + rr[k], 1);
        colp[pos] = cc[k];
        v12[pos] = make_float2(v1, v2);
    }
}

// row softmax over both components, in place, warp per row
__global__ void __launch_bounds__(256) k_softmax(const int* __restrict__ rowptr,
                                                 float2* __restrict__ v12) {
    int r = (blockIdx.x * blockDim.x + threadIdx.x) >> 5;
    int lane = threadIdx.x & 31;
    if (r >= NROWS) return;
    int s = rowptr[r], e = rowptr[r + 1];
    int len = e - s;
    if (len == 0) return;
    if (len <= 128) {
        float2 vals[4];
        int cnt = 0;
        float m1 = -1e30f, m2 = -1e30f;
        for (int j = s + lane; j < e; j += 32) {
            float2 v = v12[j];
            vals[cnt++] = v;
            m1 = fmaxf(m1, v.x); m2 = fmaxf(m2, v.y);
        }
        m1 = warp_max(m1); m2 = warp_max(m2);
        float s1 = 0.f, s2 = 0.f;
        #pragma unroll
        for (int k = 0; k < 4; k++) if (k < cnt) {
            vals[k].x = expf(vals[k].x - m1);
            vals[k].y = expf(vals[k].y - m2);
            s1 += vals[k].x; s2 += vals[k].y;
        }
        s1 = warp_sum(s1); s2 = warp_sum(s2);
        float inv1 = 1.f / (s1 + 1e-12f), inv2 = 1.f / (s2 + 1e-12f);
        int k = 0;
        for (int j = s + lane; j < e; j += 32, k++)
            v12[j] = make_float2(vals[k].x * inv1, vals[k].y * inv2);
    } else {
        float m1 = -1e30f, m2 = -1e30f;
        for (int j = s + lane; j < e; j += 32) {
            float2 v = v12[j];
            m1 = fmaxf(m1, v.x); m2 = fmaxf(m2, v.y);
        }
        m1 = warp_max(m1); m2 = warp_max(m2);
        float s1 = 0.f, s2 = 0.f;
        for (int j = s + lane; j < e; j += 32) {
            float2 v = v12[j];
            s1 += expf(v.x - m1); s2 += expf(v.y - m2);
        }
        s1 = warp_sum(s1); s2 = warp_sum(s2);
        float inv1 = 1.f / (s1 + 1e-12f), inv2 = 1.f / (s2 + 1e-12f);
        for (int j = s + lane; j < e; j += 32) {
            float2 v = v12[j];
            v12[j] = make_float2(expf(v.x - m1) * inv1, expf(v.y - m2) * inv2);
        }
    }
}

// SpMM row: batched coalesced metadata + 4 edges/iter (2 gathers in flight/lane).
// 16 lanes per edge, float4 per lane. Result valid in lanes 0-15.
template<int COMP>
__device__ __forceinline__ float4 spmm_row(const float2* __restrict__ v12,
                                           const int* __restrict__ colp,
                                           int s, int e,
                                           const float4* __restrict__ x4, int lane) {
    float4 acc0 = make_float4(0.f, 0.f, 0.f, 0.f);
    float4 acc1 = make_float4(0.f, 0.f, 0.f, 0.f);
    const int half = lane >> 4;     // 0 or 1
    const int q = lane & 15;
    for (int base = s; base < e; base += 32) {
        // coalesced metadata batch: one edge per lane
        int j = base + lane;
        int c = 0; float w = 0.f;
        if (j < e) {
            c = __ldg(colp + j);
            float2 v = __ldg(v12 + j);
            w = COMP ? v.y : v.x;
        }
        int rem = min(32, e - base);
        #pragma unroll 4
        for (int k = 0; k < rem; k += 4) {
            int iA = k + half;          // edges k, k+1
            int iB = k + 2 + half;      // edges k+2, k+3
            int   cA = __shfl_sync(0xffffffffu, c, iA);
            float wA = __shfl_sync(0xffffffffu, w, iA);
            int   cB = __shfl_sync(0xffffffffu, c, iB);
            float wB = __shfl_sync(0xffffffffu, w, iB);
            if (iA >= rem) wA = 0.f;    // masked edges: c==0 (safe), w==0
            if (iB >= rem) wB = 0.f;
            float4 xA = __ldg(x4 + (size_t)cA * 16 + q);
            float4 xB = __ldg(x4 + (size_t)cB * 16 + q);
            acc0.x += wA * xA.x; acc0.y += wA * xA.y; acc0.z += wA * xA.z; acc0.w += wA * xA.w;
            acc1.x += wB * xB.x; acc1.y += wB * xB.y; acc1.z += wB * xB.z; acc1.w += wB * xB.w;
        }
    }
    acc0.x += acc1.x; acc0.y += acc1.y; acc0.z += acc1.z; acc0.w += acc1.w;
    acc0.x += __shfl_down_sync(0xffffffffu, acc0.x, 16);
    acc0.y += __shfl_down_sync(0xffffffffu, acc0.y, 16);
    acc0.z += __shfl_down_sync(0xffffffffu, acc0.z, 16);
    acc0.w += __shfl_down_sync(0xffffffffu, acc0.w, 16);
    return acc0;
}

// fused: both user SpMMs + attention combine -> u_out  (warp per user node)
template<int COMP>
__global__ void __launch_bounds__(256) k_user_fused(const float4* __restrict__ uprev,
                                                    const float4* __restrict__ iprev,
                                                    const float2* __restrict__ v12,
                                                    const int* __restrict__ colp,
                                                    const int* __restrict__ rowptr,
                                                    const float* __restrict__ a1W,
                                                    const float* __restrict__ a1b,
                                                    const float* __restrict__ a2w,
                                                    const float* __restrict__ a2b,
                                                    int k, float4* __restrict__ out) {
    int node = (blockIdx.x * blockDim.x + threadIdx.x) >> 5;
    int lane = threadIdx.x & 31;
    if (node >= NU) return;
    int s_sn = __ldg(rowptr + node),      e_sn = __ldg(rowptr + node + 1);
    int s_ci = __ldg(rowptr + NU + node), e_ci = __ldg(rowptr + NU + node + 1);
    float4 fu = spmm_row<COMP>(v12, colp, s_sn, e_sn, uprev, lane);   // u_from_u
    float4 fi = spmm_row<COMP>(v12, colp, s_ci, e_ci, iprev, lane);   // u_from_i
    int q = lane & 15;
    float4 u = make_float4(0.f, 0.f, 0.f, 0.f);
    float dint = 0.f, dsoc = 0.f;
    const float4* Wa = (const float4*)(a1W + (size_t)k * 128);
    const float4* Wb = Wa + 32;
    if (lane < 16) {
        u = __ldg(uprev + (size_t)node * 16 + q);
        float4 wa0 = __ldg(Wa + q), wa1 = __ldg(Wa + 16 + q);
        float4 wb0 = __ldg(Wb + q), wb1 = __ldg(Wb + 16 + q);
        dint = u.x*wa0.x + u.y*wa0.y + u.z*wa0.z + u.w*wa0.w
             + fi.x*wa1.x + fi.y*wa1.y + fi.z*wa1.z + fi.w*wa1.w;
        dsoc = u.x*wb0.x + u.y*wb0.y + u.z*wb0.z + u.w*wb0.w
             + fu.x*wb1.x + fu.y*wb1.y + fu.z*wb1.z + fu.w*wb1.w;
    }
    dint = warp_sum(dint); dsoc = warp_sum(dsoc);
    float aint = att_scalar(dint, a1b[k],     a2w[k],     a2b[k])     + 0.7f;
    float asoc = att_scalar(dsoc, a1b[k + 1], a2w[k + 1], a2b[k + 1]) + 0.3f;
    float sden = aint + asoc;
    float wi = 0.5f * aint / sden, ws = 0.5f * asoc / sden;
    if (lane < 16) {
        float4 o;
        o.x = 0.5f * u.x + wi * fi.x + ws * fu.x;
        o.y = 0.5f * u.y + wi * fi.y + ws * fu.y;
        o.z = 0.5f * u.z + wi * fi.z + ws * fu.z;
        o.w = 0.5f * u.w + wi * fi.w + ws * fu.w;
        out[(size_t)node * 16 + q] = o;
    }
}

// fused: item SpMM + combine -> i_out  (warp per item node)
template<int COMP>
__global__ void __launch_bounds__(256) k_item_fused(const float4* __restrict__ uprev,
                                                    const float4* __restrict__ iprev,
                                                    const float2* __restrict__ v12,
                                                    const int* __restrict__ colp,
                                                    const int* __restrict__ rowptr,
                                                    const float* __restrict__ a1W,
                                                    const float* __restrict__ a1b,
                                                    const float* __restrict__ a2w,
                                                    const float* __restrict__ a2b,
                                                    int k, float4* __restrict__ out) {
    int node = (blockIdx.x * blockDim.x + threadIdx.x) >> 5;
    int lane = threadIdx.x & 31;
    if (node >= NI) return;
    int s_ic = __ldg(rowptr + 2 * NU + node), e_ic = __ldg(rowptr + 2 * NU + node + 1);
    float4 f = spmm_row<COMP>(v12, colp, s_ic, e_ic, uprev, lane);   // i_from_u
    int q = lane & 15;
    float4 it = make_float4(0.f, 0.f, 0.f, 0.f);
    float dself = 0.f, dcust = 0.f;
    const float4* Wa = (const float4*)(a1W + (size_t)k * 128);
    const float4* Wb = Wa + 32;
    if (lane < 16) {
        it = __ldg(iprev + (size_t)node * 16 + q);
        float4 wa0 = __ldg(Wa + q), wa1 = __ldg(Wa + 16 + q);
        float4 wb0 = __ldg(Wb + q), wb1 = __ldg(Wb + 16 + q);
        dself = it.x*(wa0.x+wa1.x) + it.y*(wa0.y+wa1.y) + it.z*(wa0.z+wa1.z) + it.w*(wa0.w+wa1.w);
        dcust = it.x*wb0.x + it.y*wb0.y + it.z*wb0.z + it.w*wb0.w
              + f.x*wb1.x + f.y*wb1.y + f.z*wb1.z + f.w*wb1.w;
    }
    dself = warp_sum(dself); dcust = warp_sum(dcust);
    float aself = att_scalar(dself, a1b[k],     a2w[k],     a2b[k])     + 1.0f;
    float acust = att_scalar(dcust, a1b[k + 1], a2w[k + 1], a2b[k + 1]) + 1.0f;
    float sden = aself + acust;
    float wsf = aself / sden, wcu = acust / sden;
    if (lane < 16) {
        float4 o;
        o.x = wsf * it.x + wcu * f.x;
        o.y = wsf * it.y + wcu * f.y;
        o.z = wsf * it.z + wcu * f.z;
        o.w = wsf * it.w + wcu * f.w;
        out[(size_t)node * 16 + q] = o;
    }
}

// final scorer: warp per (user, item) pair
__global__ void __launch_bounds__(256) k_final(const float4* __restrict__ u0,
                                               const float4* __restrict__ u1,
                                               const float4* __restrict__ u2,
                                               const float4* __restrict__ i0,
                                               const float4* __restrict__ i1,
                                               const float4* __restrict__ i2,
                                               const int* __restrict__ uidx,
                                               const int* __restrict__ iidx,
                                               float* __restrict__ out, int B) {
    int b = (blockIdx.x * blockDim.x + threadIdx.x) >> 5;
    int lane = threadIdx.x & 31;
    if (b >= B) return;
    float d = 0.f;
    if (lane < 16) {
        size_t uo = (size_t)__ldg(uidx + b) * 16 + lane;
        size_t io = (size_t)__ldg(iidx + b) * 16 + lane;
        float4 a0 = __ldg(u0 + uo), c0 = __ldg(i0 + io);
        float4 a1 = __ldg(u1 + uo), c1 = __ldg(i1 + io);
        float4 a2 = __ldg(u2 + uo), c2 = __ldg(i2 + io);
        d = a0.x*c0.x + a0.y*c0.y + a0.z*c0.z + a0.w*c0.w
          + a1.x*c1.x + a1.y*c1.y + a1.z*c1.z + a1.w*c1.w
          + a2.x*c2.x + a2.y*c2.y + a2.z*c2.z + a2.w*c2.w;
    }
    d = warp_sum(d);
    if (lane == 0) out[b] = 1.f / (1.f + expf(-d));
}

// ---------------- launch ------------------------------------------------------
extern "C" void kernel_launch(void* const* d_in, const int* in_sizes, int n_in,
                              void* d_out, int out_size) {
    const float* u_emb = (const float*)d_in[0];
    const float* i_emb = (const float*)d_in[1];
    const float* snii1 = (const float*)d_in[2];
    const float* snii2 = (const float*)d_in[3];
    const float* ciii1 = (const float*)d_in[4];
    const float* ciii2 = (const float*)d_in[5];
    const float* icii1 = (const float*)d_in[6];
    const float* icii2 = (const float*)d_in[7];
    const float* law   = (const float*)d_in[8];
    const float* lab   = (const float*)d_in[9];
    const float* a1W   = (const float*)d_in[10];
    const float* a1b   = (const float*)d_in[11];
    const float* a2w   = (const float*)d_in[12];
    const float* a2b   = (const float*)d_in[13];
    const int* sn_row  = (const int*)d_in[14];
    const int* sn_col  = (const int*)d_in[15];
    const int* ci_row  = (const int*)d_in[16];
    const int* ci_col  = (const int*)d_in[17];
    const int* ic_row  = (const int*)d_in[18];
    const int* ic_col  = (const int*)d_in[19];
    const int* uidx    = (const int*)d_in[20];
    const int* iidx    = (const int*)d_in[21];
    float* out = (float*)d_out;
    int B = out_size;

    float2 *v12; int *colp, *cnt, *rowptr, *cursor, *bsum; float4 *np;
    cudaGetSymbolAddress((void**)&v12, g_v12);
    cudaGetSymbolAddress((void**)&colp, g_colp);
    cudaGetSymbolAddress((void**)&cnt, g_cnt);
    cudaGetSymbolAddress((void**)&rowptr, g_rowptr);
    cudaGetSymbolAddress((void**)&cursor, g_cursor);
    cudaGetSymbolAddress((void**)&bsum, g_bsum);
    cudaGetSymbolAddress((void**)&np, g_node);

    float4* u1 = np;
    float4* u2 = u1 + (size_t)NU * 16;
    float4* i1 = u2 + (size_t)NU * 16;
    float4* i2 = i1 + (size_t)NI * 16;
    const float4* u0 = (const float4*)u_emb;
    const float4* i0 = (const float4*)i_emb;

    const int T = 256;

    // ---- CSR build ----
    k_zero_int<<<CDIV(NROWS, T), T>>>(cnt, NROWS);
    k_hist4<<<CDIV(ES/4, T), T>>>((const int4*)sn_row, 0, ES/4, cnt);
    k_hist4<<<CDIV(EUI/4, T), T>>>((const int4*)ci_row, NU, EUI/4, cnt);
    k_hist4<<<CDIV(EIU/4, T), T>>>((const int4*)ic_row, 2*NU, EIU/4, cnt);
    k_scan1<<<NSCANBLK, 1024>>>(cnt, rowptr, bsum, NROWS);
    k_scan2<<<1, 256>>>(bsum, NSCANBLK);
    k_scan3<<<CDIV(NROWS, T), T>>>(rowptr, cursor, bsum, NROWS);

    // ---- scatter (with fused edge logits) ----
    k_scatter4<<<CDIV(ES/4, T), T>>>((const int4*)sn_row, (const int4*)sn_col,
                                     (const float4*)snii1, (const float4*)snii2,
                                     law, lab, 0, 1, 0, ES/4, cursor, colp, v12);
    k_scatter4<<<CDIV(EUI/4, T), T>>>((const int4*)ci_row, (const int4*)ci_col,
                                      (const float4*)ciii1, (const float4*)ciii2,
                                      law, lab, 2, 3, NU, EUI/4, cursor, colp, v12);
    k_scatter4<<<CDIV(EIU/4, T), T>>>((const int4*)ic_row, (const int4*)ic_col,
                                      (const float4*)icii1, (const float4*)icii2,
                                      law, lab, 4, 5, 2*NU, EIU/4, cursor, colp, v12);

    // ---- row softmax ----
    k_softmax<<<CDIV(NROWS * 32, T), T>>>(rowptr, v12);

    // ---- layer 1 (fused SpMM + combine) ----
    k_user_fused<0><<<CDIV(NU * 32, T), T>>>(u0, i0, v12, colp, rowptr, a1W, a1b, a2w, a2b, 0, u1);
    k_item_fused<0><<<CDIV(NI * 32, T), T>>>(u0, i0, v12, colp, rowptr, a1W, a1b, a2w, a2b, 4, i1);

    // ---- layer 2 ----
    k_user_fused<1><<<CDIV(NU * 32, T), T>>>(u1, i1, v12, colp, rowptr, a1W, a1b, a2w, a2b, 2, u2);
    k_item_fused<1><<<CDIV(NI * 32, T), T>>>(u1, i1, v12, colp, rowptr, a1W, a1b, a2w, a2b, 6, i2);

    // ---- final ----
    k_final<<<CDIV(B * 32, T), T>>>(u0, u1, u2, i0, i1, i2, uidx, iidx, out, B);
}

// round 5
// speedup vs baseline: 1.1848x; 1.0913x over previous
#include <cuda_runtime.h>
#include <math.h>

#define NU 100000
#define NI 50000
#define DD 64
#define ES 800000
#define EUI 1000000
#define EIU 1000000
#define ETOT (ES + EUI + EIU)
#define NROWS (2 * NU + NI)
#define NSCANBLK ((NROWS + 2047) / 2048)
#define ALPHA_LRELU 0.2f
#define CDIV(a,b) (((a)+(b)-1)/(b))

// ---------------- scratch (device globals; no runtime allocation) -------------
__device__ float2 g_v12[ETOT];            // exp(logit) pairs, row-sorted
__device__ int    g_colp[ETOT];           // col, row-sorted
__device__ float2 g_sums[NROWS];          // per-row sums of exp (comp1, comp2)
__device__ int    g_cnt[NROWS];
__device__ int    g_rowptr[NROWS + 1];
__device__ int    g_cursor[NROWS];
__device__ int    g_bsum[NSCANBLK + 1];
__device__ float4 g_node[(2*NU + 2*NI) * 16];   // u1, u2, i1, i2

// ---------------- helpers ------------------------------------------------------
__device__ __forceinline__ float warp_sum(float v) {
    #pragma unroll
    for (int o = 16; o; o >>= 1) v += __shfl_xor_sync(0xffffffffu, v, o);
    return v;
}
__device__ __forceinline__ float att_scalar(float dot, float b1, float w2, float b2) {
    float h = tanhf(dot + b1);
    float g = h * w2 + b2;
    g = g > 0.f ? g : ALPHA_LRELU * g;
    return expf(g);
}

// ---------------- preprocessing -------------------------------------------------
__global__ void k_zero(int* __restrict__ cnt, float2* __restrict__ sums) {
    int i = blockIdx.x * blockDim.x + threadIdx.x;
    if (i < NROWS) {
        cnt[i] = 0;
        sums[i] = make_float2(0.f, 0.f);
    }
}

// one kernel for all three edge lists
__global__ void k_hist_all(const int4* __restrict__ sn_row, const int4* __restrict__ ci_row,
                           const int4* __restrict__ ic_row, int* __restrict__ cnt) {
    int i = blockIdx.x * blockDim.x + threadIdx.x;
    int4 r; int base;
    if (i < ES/4) { r = sn_row[i]; base = 0; }
    else if (i < (ES+EUI)/4) { r = ci_row[i - ES/4]; base = NU; }
    else if (i < ETOT/4) { r = ic_row[i - (ES+EUI)/4]; base = 2*NU; }
    else return;
    atomicAdd(cnt + base + r.x, 1);
    atomicAdd(cnt + base + r.y, 1);
    atomicAdd(cnt + base + r.z, 1);
    atomicAdd(cnt + base + r.w, 1);
}

__global__ void __launch_bounds__(1024) k_scan1(const int* __restrict__ cnt,
                                                int* __restrict__ out,
                                                int* __restrict__ bsum, int n) {
    __shared__ int sh[1024];
    int t = threadIdx.x;
    int i0 = blockIdx.x * 2048 + 2 * t;
    int c0 = (i0 < n) ? cnt[i0] : 0;
    int c1 = (i0 + 1 < n) ? cnt[i0 + 1] : 0;
    int p = c0 + c1;
    sh[t] = p;
    __syncthreads();
    #pragma unroll
    for (int off = 1; off < 1024; off <<= 1) {
        int add = (t >= off) ? sh[t - off] : 0;
        __syncthreads();
        sh[t] += add;
        __syncthreads();
    }
    int excl = sh[t] - p;
    if (i0 < n) out[i0] = excl;
    if (i0 + 1 < n) out[i0 + 1] = excl + c0;
    if (t == 1023) bsum[blockIdx.x] = sh[t];
}

__global__ void __launch_bounds__(256) k_scan2(int* __restrict__ bsum, int nb) {
    __shared__ int sh[256];
    int t = threadIdx.x;
    int v = (t < nb) ? bsum[t] : 0;
    sh[t] = v;
    __syncthreads();
    #pragma unroll
    for (int off = 1; off < 256; off <<= 1) {
        int add = (t >= off) ? sh[t - off] : 0;
        __syncthreads();
        sh[t] += add;
        __syncthreads();
    }
    if (t < nb) bsum[t] = sh[t] - v;
}

__global__ void k_scan3(int* __restrict__ rowptr, int* __restrict__ cursor,
                        const int* __restrict__ bsum, int n) {
    int i = blockIdx.x * blockDim.x + threadIdx.x;
    if (i < n) {
        int v = rowptr[i] + bsum[i >> 11];
        rowptr[i] = v;
        cursor[i] = v;
    }
    if (i == 0) rowptr[n] = ETOT;
}

// scatter + fused logit + exp + row-sum accumulation, all three lists, 4 edges/thread
__global__ void k_scatter_all(const int4* __restrict__ sn_row, const int4* __restrict__ sn_col,
                              const float4* __restrict__ snii1, const float4* __restrict__ snii2,
                              const int4* __restrict__ ci_row, const int4* __restrict__ ci_col,
                              const float4* __restrict__ ciii1, const float4* __restrict__ ciii2,
                              const int4* __restrict__ ic_row, const int4* __restrict__ ic_col,
                              const float4* __restrict__ icii1, const float4* __restrict__ icii2,
                              const float* __restrict__ law, const float* __restrict__ lab,
                              int* __restrict__ cursor, int* __restrict__ colp,
                              float2* __restrict__ v12, float2* __restrict__ sums) {
    int i = blockIdx.x * blockDim.x + threadIdx.x;
    int4 r, c; float4 a, b; int base, j1, j2;
    if (i < ES/4) {
        r = sn_row[i]; c = sn_col[i]; a = snii1[i]; b = snii2[i]; base = 0; j1 = 0; j2 = 1;
    } else if (i < (ES+EUI)/4) {
        int ii = i - ES/4;
        r = ci_row[ii]; c = ci_col[ii]; a = ciii1[ii]; b = ciii2[ii]; base = NU; j1 = 2; j2 = 3;
    } else if (i < ETOT/4) {
        int ii = i - (ES+EUI)/4;
        r = ic_row[ii]; c = ic_col[ii]; a = icii1[ii]; b = icii2[ii]; base = 2*NU; j1 = 4; j2 = 5;
    } else return;
    float w1 = law[j1], b1 = lab[j1], w2 = law[j2], b2 = lab[j2];
    int rr[4] = {r.x, r.y, r.z, r.w};
    int cc[4] = {c.x, c.y, c.z, c.w};
    float aa[4] = {a.x, a.y, a.z, a.w};
    float bb[4] = {b.x, b.y, b.z, b.w};
    #pragma unroll
    for (int k = 0; k < 4; k++) {
        float x1 = aa[k] * w1 + b1;
        float x2 = bb[k] * w2 + b2;
        // exp(exp(sigmoid(x))) — no max subtraction needed: inner value in [1, e]
        float e1 = expf(expf(1.f / (1.f + expf(-x1))));
        float e2 = expf(expf(1.f / (1.f + expf(-x2))));
        int row = base + rr[k];
        int pos = atomicAdd(cursor + row, 1);
        colp[pos] = cc[k];
        v12[pos] = make_float2(e1, e2);
        atomicAdd(&sums[row].x, e1);
        atomicAdd(&sums[row].y, e2);
    }
}

// ---------------- SpMM primitives ----------------------------------------------
// dual-row SpMM: interleaves gathers of two rows to overlap L2 latency.
// 16 lanes per edge, float4 per lane. Results valid in lanes 0-15.
template<int COMP>
__device__ __forceinline__ void spmm_dual(const float2* __restrict__ v12,
                                          const int* __restrict__ colp,
                                          int s1, int e1, float inv1,
                                          int s2, int e2, float inv2,
                                          const float4* __restrict__ x1,
                                          const float4* __restrict__ x2,
                                          int lane, float4& o1, float4& o2) {
    float4 acc1 = make_float4(0.f, 0.f, 0.f, 0.f);
    float4 acc2 = make_float4(0.f, 0.f, 0.f, 0.f);
    const int half = lane >> 4;
    const int q = lane & 15;
    int base1 = s1, base2 = s2;
    while (base1 < e1 || base2 < e2) {
        int c1 = 0, c2 = 0; float w1 = 0.f, w2 = 0.f;
        int rem1 = 0, rem2 = 0;
        if (base1 < e1) {
            rem1 = min(32, e1 - base1);
            int j = base1 + lane;
            if (j < e1) {
                c1 = __ldg(colp + j);
                float2 v = __ldg(v12 + j);
                w1 = (COMP ? v.y : v.x) * inv1;
            }
        }
        if (base2 < e2) {
            rem2 = min(32, e2 - base2);
            int j = base2 + lane;
            if (j < e2) {
                c2 = __ldg(colp + j);
                float2 v = __ldg(v12 + j);
                w2 = (COMP ? v.y : v.x) * inv2;
            }
        }
        int rem = max(rem1, rem2);
        for (int k = 0; k < rem; k += 2) {
            int iA = k + half;
            if (k < rem1) {          // warp-uniform
                int   cA = __shfl_sync(0xffffffffu, c1, iA);
                float wA = __shfl_sync(0xffffffffu, w1, iA);
                float4 x = __ldg(x1 + (size_t)cA * 16 + q);
                acc1.x += wA * x.x; acc1.y += wA * x.y; acc1.z += wA * x.z; acc1.w += wA * x.w;
            }
            if (k < rem2) {          // warp-uniform
                int   cB = __shfl_sync(0xffffffffu, c2, iA);
                float wB = __shfl_sync(0xffffffffu, w2, iA);
                float4 x = __ldg(x2 + (size_t)cB * 16 + q);
                acc2.x += wB * x.x; acc2.y += wB * x.y; acc2.z += wB * x.z; acc2.w += wB * x.w;
            }
        }
        base1 += 32; base2 += 32;
    }
    acc1.x += __shfl_down_sync(0xffffffffu, acc1.x, 16);
    acc1.y += __shfl_down_sync(0xffffffffu, acc1.y, 16);
    acc1.z += __shfl_down_sync(0xffffffffu, acc1.z, 16);
    acc1.w += __shfl_down_sync(0xffffffffu, acc1.w, 16);
    acc2.x += __shfl_down_sync(0xffffffffu, acc2.x, 16);
    acc2.y += __shfl_down_sync(0xffffffffu, acc2.y, 16);
    acc2.z += __shfl_down_sync(0xffffffffu, acc2.z, 16);
    acc2.w += __shfl_down_sync(0xffffffffu, acc2.w, 16);
    o1 = acc1; o2 = acc2;
}

// single-row SpMM with 4 edges/iter (2 gathers in flight per lane)
template<int COMP>
__device__ __forceinline__ float4 spmm_single(const float2* __restrict__ v12,
                                              const int* __restrict__ colp,
                                              int s, int e, float inv,
                                              const float4* __restrict__ x4, int lane) {
    float4 acc0 = make_float4(0.f, 0.f, 0.f, 0.f);
    float4 acc1 = make_float4(0.f, 0.f, 0.f, 0.f);
    const int half = lane >> 4;
    const int q = lane & 15;
    for (int base = s; base < e; base += 32) {
        int j = base + lane;
        int c = 0; float w = 0.f;
        if (j < e) {
            c = __ldg(colp + j);
            float2 v = __ldg(v12 + j);
            w = (COMP ? v.y : v.x) * inv;
        }
        int rem = min(32, e - base);
        for (int k = 0; k < rem; k += 4) {
            int iA = k + half;
            int iB = k + 2 + half;
            int   cA = __shfl_sync(0xffffffffu, c, iA);
            float wA = __shfl_sync(0xffffffffu, w, iA);
            int   cB = __shfl_sync(0xffffffffu, c, iB);
            float wB = __shfl_sync(0xffffffffu, w, iB);
            if (iB >= rem) wB = 0.f;
            float4 xA = __ldg(x4 + (size_t)cA * 16 + q);
            float4 xB = __ldg(x4 + (size_t)cB * 16 + q);
            acc0.x += wA * xA.x; acc0.y += wA * xA.y; acc0.z += wA * xA.z; acc0.w += wA * xA.w;
            acc1.x += wB * xB.x; acc1.y += wB * xB.y; acc1.z += wB * xB.z; acc1.w += wB * xB.w;
        }
    }
    acc0.x += acc1.x; acc0.y += acc1.y; acc0.z += acc1.z; acc0.w += acc1.w;
    acc0.x += __shfl_down_sync(0xffffffffu, acc0.x, 16);
    acc0.y += __shfl_down_sync(0xffffffffu, acc0.y, 16);
    acc0.z += __shfl_down_sync(0xffffffffu, acc0.z, 16);
    acc0.w += __shfl_down_sync(0xffffffffu, acc0.w, 16);
    return acc0;
}

// ---------------- merged layer kernel (user + item nodes in one grid) ----------
template<int COMP>
__global__ void __launch_bounds__(256) k_layer(const float4* __restrict__ uprev,
                                               const float4* __restrict__ iprev,
                                               const float2* __restrict__ v12,
                                               const int* __restrict__ colp,
                                               const int* __restrict__ rowptr,
                                               const float2* __restrict__ sums,
                                               const float* __restrict__ a1W,
                                               const float* __restrict__ a1b,
                                               const float* __restrict__ a2w,
                                               const float* __restrict__ a2b,
                                               int ku, int ki,
                                               float4* __restrict__ u_out,
                                               float4* __restrict__ i_out) {
    int warp = (blockIdx.x * blockDim.x + threadIdx.x) >> 5;
    int lane = threadIdx.x & 31;
    int q = lane & 15;
    if (warp < NU) {
        int node = warp;
        int s_sn = __ldg(rowptr + node),      e_sn = __ldg(rowptr + node + 1);
        int s_ci = __ldg(rowptr + NU + node), e_ci = __ldg(rowptr + NU + node + 1);
        float2 sm_sn = __ldg(sums + node);
        float2 sm_ci = __ldg(sums + NU + node);
        float inv_sn = 1.f / ((COMP ? sm_sn.y : sm_sn.x) + 1e-12f);
        float inv_ci = 1.f / ((COMP ? sm_ci.y : sm_ci.x) + 1e-12f);
        float4 fu, fi;
        spmm_dual<COMP>(v12, colp, s_sn, e_sn, inv_sn, s_ci, e_ci, inv_ci,
                        uprev, iprev, lane, fu, fi);
        int k = ku;
        float4 u = make_float4(0.f, 0.f, 0.f, 0.f);
        float dint = 0.f, dsoc = 0.f;
        const float4* Wa = (const float4*)(a1W + (size_t)k * 128);
        const float4* Wb = Wa + 32;
        if (lane < 16) {
            u = __ldg(uprev + (size_t)node * 16 + q);
            float4 wa0 = __ldg(Wa + q), wa1 = __ldg(Wa + 16 + q);
            float4 wb0 = __ldg(Wb + q), wb1 = __ldg(Wb + 16 + q);
            dint = u.x*wa0.x + u.y*wa0.y + u.z*wa0.z + u.w*wa0.w
                 + fi.x*wa1.x + fi.y*wa1.y + fi.z*wa1.z + fi.w*wa1.w;
            dsoc = u.x*wb0.x + u.y*wb0.y + u.z*wb0.z + u.w*wb0.w
                 + fu.x*wb1.x + fu.y*wb1.y + fu.z*wb1.z + fu.w*wb1.w;
        }
        dint = warp_sum(dint); dsoc = warp_sum(dsoc);
        float aint = att_scalar(dint, a1b[k],     a2w[k],     a2b[k])     + 0.7f;
        float asoc = att_scalar(dsoc, a1b[k + 1], a2w[k + 1], a2b[k + 1]) + 0.3f;
        float sden = aint + asoc;
        float wi = 0.5f * aint / sden, ws = 0.5f * asoc / sden;
        if (lane < 16) {
            float4 o;
            o.x = 0.5f * u.x + wi * fi.x + ws * fu.x;
            o.y = 0.5f * u.y + wi * fi.y + ws * fu.y;
            o.z = 0.5f * u.z + wi * fi.z + ws * fu.z;
            o.w = 0.5f * u.w + wi * fi.w + ws * fu.w;
            u_out[(size_t)node * 16 + q] = o;
        }
    } else {
        int node = warp - NU;
        if (node >= NI) return;
        int s_ic = __ldg(rowptr + 2 * NU + node), e_ic = __ldg(rowptr + 2 * NU + node + 1);
        float2 sm = __ldg(sums + 2 * NU + node);
        float inv = 1.f / ((COMP ? sm.y : sm.x) + 1e-12f);
        float4 f = spmm_single<COMP>(v12, colp, s_ic, e_ic, inv, uprev, lane);
        int k = ki;
        float4 it = make_float4(0.f, 0.f, 0.f, 0.f);
        float dself = 0.f, dcust = 0.f;
        const float4* Wa = (const float4*)(a1W + (size_t)k * 128);
        const float4* Wb = Wa + 32;
        if (lane < 16) {
            it = __ldg(iprev + (size_t)node * 16 + q);
            float4 wa0 = __ldg(Wa + q), wa1 = __ldg(Wa + 16 + q);
            float4 wb0 = __ldg(Wb + q), wb1 = __ldg(Wb + 16 + q);
            dself = it.x*(wa0.x+wa1.x) + it.y*(wa0.y+wa1.y) + it.z*(wa0.z+wa1.z) + it.w*(wa0.w+wa1.w);
            dcust = it.x*wb0.x + it.y*wb0.y + it.z*wb0.z + it.w*wb0.w
                  + f.x*wb1.x + f.y*wb1.y + f.z*wb1.z + f.w*wb1.w;
        }
        dself = warp_sum(dself); dcust = warp_sum(dcust);
        float aself = att_scalar(dself, a1b[k],     a2w[k],     a2b[k])     + 1.0f;
        float acust = att_scalar(dcust, a1b[k + 1], a2w[k + 1], a2b[k + 1]) + 1.0f;
        float sden = aself + acust;
        float wsf = aself / sden, wcu = acust / sden;
        if (lane < 16) {
            float4 o;
            o.x = wsf * it.x + wcu * f.x;
            o.y = wsf * it.y + wcu * f.y;
            o.z = wsf * it.z + wcu * f.z;
            o.w = wsf * it.w + wcu * f.w;
            i_out[(size_t)node * 16 + q] = o;
        }
    }
}

// final scorer: warp per (user, item) pair
__global__ void __launch_bounds__(256) k_final(const float4* __restrict__ u0,
                                               const float4* __restrict__ u1,
                                               const float4* __restrict__ u2,
                                               const float4* __restrict__ i0,
                                               const float4* __restrict__ i1,
                                               const float4* __restrict__ i2,
                                               const int* __restrict__ uidx,
                                               const int* __restrict__ iidx,
                                               float* __restrict__ out, int B) {
    int b = (blockIdx.x * blockDim.x + threadIdx.x) >> 5;
    int lane = threadIdx.x & 31;
    if (b >= B) return;
    float d = 0.f;
    if (lane < 16) {
        size_t uo = (size_t)__ldg(uidx + b) * 16 + lane;
        size_t io = (size_t)__ldg(iidx + b) * 16 + lane;
        float4 a0 = __ldg(u0 + uo), c0 = __ldg(i0 + io);
        float4 a1 = __ldg(u1 + uo), c1 = __ldg(i1 + io);
        float4 a2 = __ldg(u2 + uo), c2 = __ldg(i2 + io);
        d = a0.x*c0.x + a0.y*c0.y + a0.z*c0.z + a0.w*c0.w
          + a1.x*c1.x + a1.y*c1.y + a1.z*c1.z + a1.w*c1.w
          + a2.x*c2.x + a2.y*c2.y + a2.z*c2.z + a2.w*c2.w;
    }
    d = warp_sum(d);
    if (lane == 0) out[b] = 1.f / (1.f + expf(-d));
}

// ---------------- launch ------------------------------------------------------
extern "C" void kernel_launch(void* const* d_in, const int* in_sizes, int n_in,
                              void* d_out, int out_size) {
    const float* u_emb = (const float*)d_in[0];
    const float* i_emb = (const float*)d_in[1];
    const float* snii1 = (const float*)d_in[2];
    const float* snii2 = (const float*)d_in[3];
    const float* ciii1 = (const float*)d_in[4];
    const float* ciii2 = (const float*)d_in[5];
    const float* icii1 = (const float*)d_in[6];
    const float* icii2 = (const float*)d_in[7];
    const float* law   = (const float*)d_in[8];
    const float* lab   = (const float*)d_in[9];
    const float* a1W   = (const float*)d_in[10];
    const float* a1b   = (const float*)d_in[11];
    const float* a2w   = (const float*)d_in[12];
    const float* a2b   = (const float*)d_in[13];
    const int* sn_row  = (const int*)d_in[14];
    const int* sn_col  = (const int*)d_in[15];
    const int* ci_row  = (const int*)d_in[16];
    const int* ci_col  = (const int*)d_in[17];
    const int* ic_row  = (const int*)d_in[18];
    const int* ic_col  = (const int*)d_in[19];
    const int* uidx    = (const int*)d_in[20];
    const int* iidx    = (const int*)d_in[21];
    float* out = (float*)d_out;
    int B = out_size;

    float2 *v12, *sums; int *colp, *cnt, *rowptr, *cursor, *bsum; float4 *np;
    cudaGetSymbolAddress((void**)&v12, g_v12);
    cudaGetSymbolAddress((void**)&sums, g_sums);
    cudaGetSymbolAddress((void**)&colp, g_colp);
    cudaGetSymbolAddress((void**)&cnt, g_cnt);
    cudaGetSymbolAddress((void**)&rowptr, g_rowptr);
    cudaGetSymbolAddress((void**)&cursor, g_cursor);
    cudaGetSymbolAddress((void**)&bsum, g_bsum);
    cudaGetSymbolAddress((void**)&np, g_node);

    float4* u1 = np;
    float4* u2 = u1 + (size_t)NU * 16;
    float4* i1 = u2 + (size_t)NU * 16;
    float4* i2 = i1 + (size_t)NI * 16;
    const float4* u0 = (const float4*)u_emb;
    const float4* i0 = (const float4*)i_emb;

    const int T = 256;

    // ---- CSR build + edge weights ----
    k_zero<<<CDIV(NROWS, T), T>>>(cnt, sums);
    k_hist_all<<<CDIV(ETOT/4, T), T>>>((const int4*)sn_row, (const int4*)ci_row,
                                       (const int4*)ic_row, cnt);
    k_scan1<<<NSCANBLK, 1024>>>(cnt, rowptr, bsum, NROWS);
    k_scan2<<<1, 256>>>(bsum, NSCANBLK);
    k_scan3<<<CDIV(NROWS, T), T>>>(rowptr, cursor, bsum, NROWS);
    k_scatter_all<<<CDIV(ETOT/4, T), T>>>((const int4*)sn_row, (const int4*)sn_col,
                                          (const float4*)snii1, (const float4*)snii2,
                                          (const int4*)ci_row, (const int4*)ci_col,
                                          (const float4*)ciii1, (const float4*)ciii2,
                                          (const int4*)ic_row, (const int4*)ic_col,
                                          (const float4*)icii1, (const float4*)icii2,
                                          law, lab, cursor, colp, v12, sums);

    // ---- layers (merged user+item) ----
    int layer_warps = NU + NI;
    k_layer<0><<<CDIV(layer_warps * 32, T), T>>>(u0, i0, v12, colp, rowptr, sums,
                                                 a1W, a1b, a2w, a2b, 0, 4, u1, i1);
    k_layer<1><<<CDIV(layer_warps * 32, T), T>>>(u1, i1, v12, colp, rowptr, sums,
                                                 a1W, a1b, a2w, a2b, 2, 6, u2, i2);

    // ---- final ----
    k_final<<<CDIV(B * 32, T), T>>>(u0, u1, u2, i0, i1, i2, uidx, iidx, out, B);
}

// round 6
// speedup vs baseline: 1.3529x; 1.1419x over previous
#include <cuda_runtime.h>
#include <math.h>

#define NU 100000
#define NI 50000
#define DD 64
#define ES 800000
#define EUI 1000000
#define EIU 1000000
#define ETOT (ES + EUI + EIU)
#define NROWS (2 * NU + NI)
#define NSCANBLK ((NROWS + 2047) / 2048)
#define ALPHA_LRELU 0.2f
#define CDIV(a,b) (((a)+(b)-1)/(b))

// ---------------- scratch (device globals; no runtime allocation) -------------
// meta record per edge: {col, bits(e1), bits(e2), pad} — one 16B store on scatter
__device__ int4  g_meta[ETOT];
__device__ int   g_cnt[NROWS];                 // zero at load; re-zeroed by scan each call
__device__ int   g_rowptr[NROWS + 1];
__device__ int   g_cursor[NROWS];
__device__ unsigned long long g_status[NSCANBLK];  // lookback statuses (reset by hist)
__device__ float4 g_node[(2*NU + 2*NI) * 16];  // u1, u2, i1, i2

// ---------------- helpers ------------------------------------------------------
__device__ __forceinline__ float warp_sum(float v) {
    #pragma unroll
    for (int o = 16; o; o >>= 1) v += __shfl_xor_sync(0xffffffffu, v, o);
    return v;
}
__device__ __forceinline__ float att_scalar(float dot, float b1, float w2, float b2) {
    float h = tanhf(dot + b1);
    float g = h * w2 + b2;
    g = g > 0.f ? g : ALPHA_LRELU * g;
    return expf(g);
}

// ---------------- preprocessing -------------------------------------------------
// hist over all three edge lists; also resets lookback statuses for the scan
__global__ void k_hist_all(const int4* __restrict__ sn_row, const int4* __restrict__ ci_row,
                           const int4* __restrict__ ic_row, int* __restrict__ cnt,
                           unsigned long long* __restrict__ status) {
    int i = blockIdx.x * blockDim.x + threadIdx.x;
    if (i < NSCANBLK) status[i] = 0ull;
    int4 r; int base;
    if (i < ES/4) { r = sn_row[i]; base = 0; }
    else if (i < (ES+EUI)/4) { r = ci_row[i - ES/4]; base = NU; }
    else if (i < ETOT/4) { r = ic_row[i - (ES+EUI)/4]; base = 2*NU; }
    else return;
    atomicAdd(cnt + base + r.x, 1);
    atomicAdd(cnt + base + r.y, 1);
    atomicAdd(cnt + base + r.z, 1);
    atomicAdd(cnt + base + r.w, 1);
}

// single-pass scan with decoupled lookback (NSCANBLK = 123 blocks, all resident).
// Also zeroes cnt in place for the next call.
__global__ void __launch_bounds__(1024) k_scan(int* __restrict__ cnt,
                                               int* __restrict__ rowptr,
                                               int* __restrict__ cursor,
                                               unsigned long long* status) {
    __shared__ int sh[1024];
    __shared__ int s_prefix;
    int t = threadIdx.x, b = blockIdx.x;
    int i0 = b * 2048 + 2 * t;
    int c0 = (i0 < NROWS) ? cnt[i0] : 0;
    int c1 = (i0 + 1 < NROWS) ? cnt[i0 + 1] : 0;
    if (i0 < NROWS) cnt[i0] = 0;
    if (i0 + 1 < NROWS) cnt[i0 + 1] = 0;
    int p = c0 + c1;
    sh[t] = p;
    __syncthreads();
    #pragma unroll
    for (int off = 1; off < 1024; off <<= 1) {
        int add = (t >= off) ? sh[t - off] : 0;
        __syncthreads();
        sh[t] += add;
        __syncthreads();
    }
    if (t == 1023) {
        long long total = sh[1023];
        atomicExch(status + b, ((unsigned long long)total << 2) | 1ull);
        long long prefix = 0;
        for (int pb = b - 1; pb >= 0; ) {
            unsigned long long s = *((volatile unsigned long long*)(status + pb));
            unsigned st = (unsigned)(s & 3ull);
            if (st == 0u) continue;            // spin
            prefix += (long long)(s >> 2);
            if (st == 2u) break;               // inclusive found
            pb--;
        }
        atomicExch(status + b, ((unsigned long long)(prefix + total) << 2) | 2ull);
        s_prefix = (int)prefix;
    }
    __syncthreads();
    int excl = sh[t] - p + s_prefix;
    if (i0 < NROWS)     { rowptr[i0] = excl;          cursor[i0] = excl; }
    if (i0 + 1 < NROWS) { rowptr[i0 + 1] = excl + c0; cursor[i0 + 1] = excl + c0; }
    if (b == 0 && t == 0) rowptr[NROWS] = ETOT;
}

// scatter + fused logit + exp, all three lists, 4 edges/thread, one 16B store/edge
__global__ void k_scatter_all(const int4* __restrict__ sn_row, const int4* __restrict__ sn_col,
                              const float4* __restrict__ snii1, const float4* __restrict__ snii2,
                              const int4* __restrict__ ci_row, const int4* __restrict__ ci_col,
                              const float4* __restrict__ ciii1, const float4* __restrict__ ciii2,
                              const int4* __restrict__ ic_row, const int4* __restrict__ ic_col,
                              const float4* __restrict__ icii1, const float4* __restrict__ icii2,
                              const float* __restrict__ law, const float* __restrict__ lab,
                              int* __restrict__ cursor, int4* __restrict__ meta) {
    int i = blockIdx.x * blockDim.x + threadIdx.x;
    int4 r, c; float4 a, b; int base, j1, j2;
    if (i < ES/4) {
        r = sn_row[i]; c = sn_col[i]; a = snii1[i]; b = snii2[i]; base = 0; j1 = 0; j2 = 1;
    } else if (i < (ES+EUI)/4) {
        int ii = i - ES/4;
        r = ci_row[ii]; c = ci_col[ii]; a = ciii1[ii]; b = ciii2[ii]; base = NU; j1 = 2; j2 = 3;
    } else if (i < ETOT/4) {
        int ii = i - (ES+EUI)/4;
        r = ic_row[ii]; c = ic_col[ii]; a = icii1[ii]; b = icii2[ii]; base = 2*NU; j1 = 4; j2 = 5;
    } else return;
    float w1 = law[j1], b1 = lab[j1], w2 = law[j2], b2 = lab[j2];
    int rr[4] = {r.x, r.y, r.z, r.w};
    int cc[4] = {c.x, c.y, c.z, c.w};
    float aa[4] = {a.x, a.y, a.z, a.w};
    float bb[4] = {b.x, b.y, b.z, b.w};
    #pragma unroll
    for (int k = 0; k < 4; k++) {
        float x1 = aa[k] * w1 + b1;
        float x2 = bb[k] * w2 + b2;
        // exp(exp(sigmoid(x))) — inner value in [1, e]; softmax max-shift unnecessary
        float e1 = expf(expf(1.f / (1.f + expf(-x1))));
        float e2 = expf(expf(1.f / (1.f + expf(-x2))));
        int pos = atomicAdd(cursor + base + rr[k], 1);
        int4 rec;
        rec.x = cc[k];
        rec.y = __float_as_int(e1);
        rec.z = __float_as_int(e2);
        rec.w = 0;
        meta[pos] = rec;
    }
}

// ---------------- SpMM primitives ----------------------------------------------
// dual-row SpMM with on-the-fly softmax normalization (row sums from metadata).
// 16 lanes per edge, float4 per lane. Results valid in lanes 0-15.
template<int COMP>
__device__ __forceinline__ void spmm_dual(const int4* __restrict__ meta,
                                          int s1, int e1, int s2, int e2,
                                          const float4* __restrict__ x1,
                                          const float4* __restrict__ x2,
                                          int lane, float4& o1, float4& o2) {
    float4 acc1 = make_float4(0.f, 0.f, 0.f, 0.f);
    float4 acc2 = make_float4(0.f, 0.f, 0.f, 0.f);
    float ws1 = 0.f, ws2 = 0.f;
    const int half = lane >> 4;
    const int q = lane & 15;
    int base1 = s1, base2 = s2;
    while (base1 < e1 || base2 < e2) {
        int c1 = 0, c2 = 0; float w1 = 0.f, w2 = 0.f;
        int rem1 = 0, rem2 = 0;
        if (base1 < e1) {
            rem1 = min(32, e1 - base1);
            int j = base1 + lane;
            if (j < e1) {
                int4 m = __ldg(meta + j);
                c1 = m.x;
                w1 = __int_as_float(COMP ? m.z : m.y);
            }
        }
        if (base2 < e2) {
            rem2 = min(32, e2 - base2);
            int j = base2 + lane;
            if (j < e2) {
                int4 m = __ldg(meta + j);
                c2 = m.x;
                w2 = __int_as_float(COMP ? m.z : m.y);
            }
        }
        ws1 += w1; ws2 += w2;
        int rem = max(rem1, rem2);
        for (int k = 0; k < rem; k += 2) {
            int iA = k + half;
            if (k < rem1) {          // warp-uniform
                int   cA = __shfl_sync(0xffffffffu, c1, iA);
                float wA = __shfl_sync(0xffffffffu, w1, iA);
                float4 x = __ldg(x1 + (size_t)cA * 16 + q);
                acc1.x += wA * x.x; acc1.y += wA * x.y; acc1.z += wA * x.z; acc1.w += wA * x.w;
            }
            if (k < rem2) {          // warp-uniform
                int   cB = __shfl_sync(0xffffffffu, c2, iA);
                float wB = __shfl_sync(0xffffffffu, w2, iA);
                float4 x = __ldg(x2 + (size_t)cB * 16 + q);
                acc2.x += wB * x.x; acc2.y += wB * x.y; acc2.z += wB * x.z; acc2.w += wB * x.w;
            }
        }
        base1 += 32; base2 += 32;
    }
    float inv1 = 1.f / (warp_sum(ws1) + 1e-12f);
    float inv2 = 1.f / (warp_sum(ws2) + 1e-12f);
    acc1.x += __shfl_down_sync(0xffffffffu, acc1.x, 16);
    acc1.y += __shfl_down_sync(0xffffffffu, acc1.y, 16);
    acc1.z += __shfl_down_sync(0xffffffffu, acc1.z, 16);
    acc1.w += __shfl_down_sync(0xffffffffu, acc1.w, 16);
    acc2.x += __shfl_down_sync(0xffffffffu, acc2.x, 16);
    acc2.y += __shfl_down_sync(0xffffffffu, acc2.y, 16);
    acc2.z += __shfl_down_sync(0xffffffffu, acc2.z, 16);
    acc2.w += __shfl_down_sync(0xffffffffu, acc2.w, 16);
    o1 = make_float4(acc1.x * inv1, acc1.y * inv1, acc1.z * inv1, acc1.w * inv1);
    o2 = make_float4(acc2.x * inv2, acc2.y * inv2, acc2.z * inv2, acc2.w * inv2);
}

// single-row SpMM, 4 edges/iter (2 gathers in flight per lane), on-the-fly norm
template<int COMP>
__device__ __forceinline__ float4 spmm_single(const int4* __restrict__ meta,
                                              int s, int e,
                                              const float4* __restrict__ x4, int lane) {
    float4 acc0 = make_float4(0.f, 0.f, 0.f, 0.f);
    float4 acc1 = make_float4(0.f, 0.f, 0.f, 0.f);
    float ws = 0.f;
    const int half = lane >> 4;
    const int q = lane & 15;
    for (int base = s; base < e; base += 32) {
        int j = base + lane;
        int c = 0; float w = 0.f;
        if (j < e) {
            int4 m = __ldg(meta + j);
            c = m.x;
            w = __int_as_float(COMP ? m.z : m.y);
        }
        ws += w;
        int rem = min(32, e - base);
        for (int k = 0; k < rem; k += 4) {
            int iA = k + half;
            int iB = k + 2 + half;
            int   cA = __shfl_sync(0xffffffffu, c, iA);
            float wA = __shfl_sync(0xffffffffu, w, iA);
            int   cB = __shfl_sync(0xffffffffu, c, iB);
            float wB = __shfl_sync(0xffffffffu, w, iB);
            if (iB >= rem) wB = 0.f;
            float4 xA = __ldg(x4 + (size_t)cA * 16 + q);
            float4 xB = __ldg(x4 + (size_t)cB * 16 + q);
            acc0.x += wA * xA.x; acc0.y += wA * xA.y; acc0.z += wA * xA.z; acc0.w += wA * xA.w;
            acc1.x += wB * xB.x; acc1.y += wB * xB.y; acc1.z += wB * xB.z; acc1.w += wB * xB.w;
        }
    }
    float inv = 1.f / (warp_sum(ws) + 1e-12f);
    acc0.x += acc1.x; acc0.y += acc1.y; acc0.z += acc1.z; acc0.w += acc1.w;
    acc0.x += __shfl_down_sync(0xffffffffu, acc0.x, 16);
    acc0.y += __shfl_down_sync(0xffffffffu, acc0.y, 16);
    acc0.z += __shfl_down_sync(0xffffffffu, acc0.z, 16);
    acc0.w += __shfl_down_sync(0xffffffffu, acc0.w, 16);
    return make_float4(acc0.x * inv, acc0.y * inv, acc0.z * inv, acc0.w * inv);
}

// ---------------- merged layer kernel (user + item nodes in one grid) ----------
template<int COMP>
__global__ void __launch_bounds__(256) k_layer(const float4* __restrict__ uprev,
                                               const float4* __restrict__ iprev,
                                               const int4* __restrict__ meta,
                                               const int* __restrict__ rowptr,
                                               const float* __restrict__ a1W,
                                               const float* __restrict__ a1b,
                                               const float* __restrict__ a2w,
                                               const float* __restrict__ a2b,
                                               int ku, int ki,
                                               float4* __restrict__ u_out,
                                               float4* __restrict__ i_out) {
    int warp = (blockIdx.x * blockDim.x + threadIdx.x) >> 5;
    int lane = threadIdx.x & 31;
    int q = lane & 15;
    if (warp < NU) {
        int node = warp;
        int s_sn = __ldg(rowptr + node),      e_sn = __ldg(rowptr + node + 1);
        int s_ci = __ldg(rowptr + NU + node), e_ci = __ldg(rowptr + NU + node + 1);
        float4 fu, fi;
        spmm_dual<COMP>(meta, s_sn, e_sn, s_ci, e_ci, uprev, iprev, lane, fu, fi);
        int k = ku;
        float4 u = make_float4(0.f, 0.f, 0.f, 0.f);
        float dint = 0.f, dsoc = 0.f;
        const float4* Wa = (const float4*)(a1W + (size_t)k * 128);
        const float4* Wb = Wa + 32;
        if (lane < 16) {
            u = __ldg(uprev + (size_t)node * 16 + q);
            float4 wa0 = __ldg(Wa + q), wa1 = __ldg(Wa + 16 + q);
            float4 wb0 = __ldg(Wb + q), wb1 = __ldg(Wb + 16 + q);
            dint = u.x*wa0.x + u.y*wa0.y + u.z*wa0.z + u.w*wa0.w
                 + fi.x*wa1.x + fi.y*wa1.y + fi.z*wa1.z + fi.w*wa1.w;
            dsoc = u.x*wb0.x + u.y*wb0.y + u.z*wb0.z + u.w*wb0.w
                 + fu.x*wb1.x + fu.y*wb1.y + fu.z*wb1.z + fu.w*wb1.w;
        }
        dint = warp_sum(dint); dsoc = warp_sum(dsoc);
        float aint = att_scalar(dint, a1b[k],     a2w[k],     a2b[k])     + 0.7f;
        float asoc = att_scalar(dsoc, a1b[k + 1], a2w[k + 1], a2b[k + 1]) + 0.3f;
        float sden = aint + asoc;
        float wi = 0.5f * aint / sden, ws = 0.5f * asoc / sden;
        if (lane < 16) {
            float4 o;
            o.x = 0.5f * u.x + wi * fi.x + ws * fu.x;
            o.y = 0.5f * u.y + wi * fi.y + ws * fu.y;
            o.z = 0.5f * u.z + wi * fi.z + ws * fu.z;
            o.w = 0.5f * u.w + wi * fi.w + ws * fu.w;
            u_out[(size_t)node * 16 + q] = o;
        }
    } else {
        int node = warp - NU;
        if (node >= NI) return;
        int s_ic = __ldg(rowptr + 2 * NU + node), e_ic = __ldg(rowptr + 2 * NU + node + 1);
        float4 f = spmm_single<COMP>(meta, s_ic, e_ic, uprev, lane);
        int k = ki;
        float4 it = make_float4(0.f, 0.f, 0.f, 0.f);
        float dself = 0.f, dcust = 0.f;
        const float4* Wa = (const float4*)(a1W + (size_t)k * 128);
        const float4* Wb = Wa + 32;
        if (lane < 16) {
            it = __ldg(iprev + (size_t)node * 16 + q);
            float4 wa0 = __ldg(Wa + q), wa1 = __ldg(Wa + 16 + q);
            float4 wb0 = __ldg(Wb + q), wb1 = __ldg(Wb + 16 + q);
            dself = it.x*(wa0.x+wa1.x) + it.y*(wa0.y+wa1.y) + it.z*(wa0.z+wa1.z) + it.w*(wa0.w+wa1.w);
            dcust = it.x*wb0.x + it.y*wb0.y + it.z*wb0.z + it.w*wb0.w
                  + f.x*wb1.x + f.y*wb1.y + f.z*wb1.z + f.w*wb1.w;
        }
        dself = warp_sum(dself); dcust = warp_sum(dcust);
        float aself = att_scalar(dself, a1b[k],     a2w[k],     a2b[k])     + 1.0f;
        float acust = att_scalar(dcust, a1b[k + 1], a2w[k + 1], a2b[k + 1]) + 1.0f;
        float sden = aself + acust;
        float wsf = aself / sden, wcu = acust / sden;
        if (lane < 16) {
            float4 o;
            o.x = wsf * it.x + wcu * f.x;
            o.y = wsf * it.y + wcu * f.y;
            o.z = wsf * it.z + wcu * f.z;
            o.w = wsf * it.w + wcu * f.w;
            i_out[(size_t)node * 16 + q] = o;
        }
    }
}

// final scorer: warp per (user, item) pair
__global__ void __launch_bounds__(256) k_final(const float4* __restrict__ u0,
                                               const float4* __restrict__ u1,
                                               const float4* __restrict__ u2,
                                               const float4* __restrict__ i0,
                                               const float4* __restrict__ i1,
                                               const float4* __restrict__ i2,
                                               const int* __restrict__ uidx,
                                               const int* __restrict__ iidx,
                                               float* __restrict__ out, int B) {
    int b = (blockIdx.x * blockDim.x + threadIdx.x) >> 5;
    int lane = threadIdx.x & 31;
    if (b >= B) return;
    float d = 0.f;
    if (lane < 16) {
        size_t uo = (size_t)__ldg(uidx + b) * 16 + lane;
        size_t io = (size_t)__ldg(iidx + b) * 16 + lane;
        float4 a0 = __ldg(u0 + uo), c0 = __ldg(i0 + io);
        float4 a1 = __ldg(u1 + uo), c1 = __ldg(i1 + io);
        float4 a2 = __ldg(u2 + uo), c2 = __ldg(i2 + io);
        d = a0.x*c0.x + a0.y*c0.y + a0.z*c0.z + a0.w*c0.w
          + a1.x*c1.x + a1.y*c1.y + a1.z*c1.z + a1.w*c1.w
          + a2.x*c2.x + a2.y*c2.y + a2.z*c2.z + a2.w*c2.w;
    }
    d = warp_sum(d);
    if (lane == 0) out[b] = 1.f / (1.f + expf(-d));
}

// ---------------- launch ------------------------------------------------------
extern "C" void kernel_launch(void* const* d_in, const int* in_sizes, int n_in,
                              void* d_out, int out_size) {
    const float* u_emb = (const float*)d_in[0];
    const float* i_emb = (const float*)d_in[1];
    const float* snii1 = (const float*)d_in[2];
    const float* snii2 = (const float*)d_in[3];
    const float* ciii1 = (const float*)d_in[4];
    const float* ciii2 = (const float*)d_in[5];
    const float* icii1 = (const float*)d_in[6];
    const float* icii2 = (const float*)d_in[7];
    const float* law   = (const float*)d_in[8];
    const float* lab   = (const float*)d_in[9];
    const float* a1W   = (const float*)d_in[10];
    const float* a1b   = (const float*)d_in[11];
    const float* a2w   = (const float*)d_in[12];
    const float* a2b   = (const float*)d_in[13];
    const int* sn_row  = (const int*)d_in[14];
    const int* sn_col  = (const int*)d_in[15];
    const int* ci_row  = (const int*)d_in[16];
    const int* ci_col  = (const int*)d_in[17];
    const int* ic_row  = (const int*)d_in[18];
    const int* ic_col  = (const int*)d_in[19];
    const int* uidx    = (const int*)d_in[20];
    const int* iidx    = (const int*)d_in[21];
    float* out = (float*)d_out;
    int B = out_size;

    int4 *meta; int *cnt, *rowptr, *cursor; unsigned long long *status; float4 *np;
    cudaGetSymbolAddress((void**)&meta, g_meta);
    cudaGetSymbolAddress((void**)&cnt, g_cnt);
    cudaGetSymbolAddress((void**)&rowptr, g_rowptr);
    cudaGetSymbolAddress((void**)&cursor, g_cursor);
    cudaGetSymbolAddress((void**)&status, g_status);
    cudaGetSymbolAddress((void**)&np, g_node);

    float4* u1 = np;
    float4* u2 = u1 + (size_t)NU * 16;
    float4* i1 = u2 + (size_t)NU * 16;
    float4* i2 = i1 + (size_t)NI * 16;
    const float4* u0 = (const float4*)u_emb;
    const float4* i0 = (const float4*)i_emb;

    const int T = 256;

    // ---- CSR build + edge weights (3 kernels) ----
    k_hist_all<<<CDIV(ETOT/4, T), T>>>((const int4*)sn_row, (const int4*)ci_row,
                                       (const int4*)ic_row, cnt, status);
    k_scan<<<NSCANBLK, 1024>>>(cnt, rowptr, cursor, status);
    k_scatter_all<<<CDIV(ETOT/4, T), T>>>((const int4*)sn_row, (const int4*)sn_col,
                                          (const float4*)snii1, (const float4*)snii2,
                                          (const int4*)ci_row, (const int4*)ci_col,
                                          (const float4*)ciii1, (const float4*)ciii2,
                                          (const int4*)ic_row, (const int4*)ic_col,
                                          (const float4*)icii1, (const float4*)icii2,
                                          law, lab, cursor, meta);

    // ---- layers (merged user+item) ----
    int layer_warps = NU + NI;
    k_layer<0><<<CDIV(layer_warps * 32, T), T>>>(u0, i0, meta, rowptr,
                                                 a1W, a1b, a2w, a2b, 0, 4, u1, i1);
    k_layer<1><<<CDIV(layer_warps * 32, T), T>>>(u1, i1, meta, rowptr,
                                                 a1W, a1b, a2w, a2b, 2, 6, u2, i2);

    // ---- final ----
    k_final<<<CDIV(B * 32, T), T>>>(u0, u1, u2, i0, i1, i2, uidx, iidx, out, B);
}